// round 2
// baseline (speedup 1.0000x reference)
#include <cuda_runtime.h>
#include <math.h>

// Problem constants
#define NB   64
#define LSEQ 510
#define DDIM 768
#define L1   128
#define KN   20
#define OUTD 300
#define NPAD 320
#define EPSV 1e-5f

// GEMM tiling
#define TM 32
#define KC 16
#define NCHUNK (DDIM / KC)   // 48
#define NBLK1 (NB * L1 / TM) // 256
#define NBLKK (NB * KN / TM) // 40
#define NBLK  (NBLK1 + NBLKK)

// Output layout (concatenated, reference tuple order)
#define H1_OFF    0
#define SCORE_OFF (NB * L1 * OUTD)                 // 2457600
#define HK_OFF    (2 * NB * L1 * OUTD)             // 4915200
#define SK_OFF    (HK_OFF + NB * KN * OUTD)        // 5299200

// Scratch
__device__ __align__(16) float g_WT[DDIM * NPAD];  // W_lin transposed+padded: [k][n]
__device__ float g_scores[NB * L1 + NB * KN];      // raw scores before softmax
__device__ int   g_mask_mode;                      // 0=uint8, 1=int32, 2=float32

// ---------------------------------------------------------------------------
// Mask dtype detection: bool masks may arrive as uint8 (1B), int32, or float32.
// uint8: bytes are 0/1, nonzero at indices !≡0 (mod 4) (contiguous suffix of 1s).
// int32: little-endian 0/1 -> nonzero bytes only at i%4==0.
// float32 1.0f: bytes 0x80/0x3f appear -> "weird" bytes (>1).
// Reading the first (n_elems) bytes is safe under every interpretation.
// ---------------------------------------------------------------------------
__global__ void detect_mask_kernel(const unsigned char* __restrict__ mk,
                                   const unsigned char* __restrict__ m1) {
    __shared__ int f_weird, f_odd;
    int t = threadIdx.x;
    if (t == 0) { f_weird = 0; f_odd = 0; }
    __syncthreads();
    int lw = 0, lo = 0;
    for (int i = t; i < NB * KN; i += 256) {
        unsigned char v = mk[i];
        if (v > 1) lw = 1;
        if (v && (i & 3)) lo = 1;
    }
    for (int i = t; i < NB * L1; i += 256) {
        unsigned char v = m1[i];
        if (v > 1) lw = 1;
        if (v && (i & 3)) lo = 1;
    }
    if (lw) atomicOr(&f_weird, 1);
    if (lo) atomicOr(&f_odd, 1);
    __syncthreads();
    if (t == 0) g_mask_mode = f_weird ? 2 : (f_odd ? 0 : 1);
}

__device__ __forceinline__ bool read_mask(const void* m, int i, int mode) {
    if (mode == 0) return ((const unsigned char*)m)[i] != 0;
    if (mode == 1) return ((const int*)m)[i] != 0;
    return ((const float*)m)[i] != 0.0f;
}

// ---------------------------------------------------------------------------
// Transpose W_lin (OUTD x DDIM) -> g_WT (DDIM x NPAD), zero pad n>=OUTD.
// ---------------------------------------------------------------------------
__global__ void transpose_w_kernel(const float* __restrict__ W) {
    __shared__ float tile[32][33];
    int k0 = blockIdx.x * 32;   // 24 tiles over DDIM
    int n0 = blockIdx.y * 32;   // 10 tiles over NPAD
    int tx = threadIdx.x, ty = threadIdx.y; // 32 x 8
    #pragma unroll
    for (int r = ty; r < 32; r += 8) {
        int n = n0 + r;
        tile[r][tx] = (n < OUTD) ? W[n * DDIM + k0 + tx] : 0.0f;
    }
    __syncthreads();
    #pragma unroll
    for (int r = ty; r < 32; r += 8) {
        g_WT[(k0 + r) * NPAD + n0 + tx] = tile[tx][r];
    }
}

// ---------------------------------------------------------------------------
// Fused: span-mean pooling + GEMM (pooled @ W_lin^T + b) + LayerNorm + score.
// Block = TM spans x NPAD outputs. 256 threads: ty=warp (8) x tx=lane (32).
// Thread computes 4 spans (m = ty*4+mm) x 10 outputs (pairs p = tx+32i).
// Packed f32x2 FMAs double fp32 throughput.
// ---------------------------------------------------------------------------
__global__ __launch_bounds__(256, 2)
void gemm_ln_kernel(const float* __restrict__ t1, const float* __restrict__ know,
                    const int* __restrict__ s1s, const int* __restrict__ s1e,
                    const int* __restrict__ sks, const int* __restrict__ ske,
                    const float* __restrict__ b_lin, const float* __restrict__ gamma,
                    const float* __restrict__ beta, const float* __restrict__ w_score,
                    const float* __restrict__ b_score, float* __restrict__ out) {
    __shared__ float As[TM][KC + 1];
    __shared__ __align__(16) float Bs[KC][NPAD];
    __shared__ float sb[NPAD], sg[NPAD], sbe[NPAD], sw[NPAD];
    __shared__ int   sm_start[TM];
    __shared__ int   sm_len[TM];
    __shared__ float sm_inv[TM];

    const int t   = threadIdx.x;
    const int blk = blockIdx.x;
    const bool isK = (blk >= NBLK1);
    const float* __restrict__ src = isK ? know : t1;
    const int tilebase = (isK ? (blk - NBLK1) : blk) * TM;
    const int per = isK ? KN : L1;

    for (int i = t; i < NPAD; i += 256) {
        sb[i]  = (i < OUTD) ? b_lin[i]   : 0.0f;
        sg[i]  = (i < OUTD) ? gamma[i]   : 0.0f;
        sbe[i] = (i < OUTD) ? beta[i]    : 0.0f;
        sw[i]  = (i < OUTD) ? w_score[i] : 0.0f;
    }
    if (t < TM) {
        int g = tilebase + t;
        int b = g / per, idx = g % per;
        int s = (isK ? sks : s1s)[b * per + idx];
        int e = (isK ? ske : s1e)[b * per + idx];
        int len = e - s; if (len < 1) len = 1;
        sm_start[t] = (b * LSEQ + s) * DDIM;
        sm_len[t]   = len;
        sm_inv[t]   = 1.0f / (float)len;
    }
    __syncthreads();

    unsigned long long acc[4][5];
    #pragma unroll
    for (int mm = 0; mm < 4; mm++)
        #pragma unroll
        for (int i = 0; i < 5; i++) acc[mm][i] = 0ULL;

    const int ty = t >> 5, tx = t & 31;

    for (int kc = 0; kc < DDIM; kc += KC) {
        // ---- A tile: pooled[m][kk] = mean over span rows (len <= 4) ----
        #pragma unroll
        for (int j = 0; j < 2; j++) {
            int e2 = t + 256 * j;            // 0..511 over 32x16
            int m  = e2 >> 4, kk = e2 & 15;
            int base = sm_start[m] + kc + kk;
            int len  = sm_len[m];
            float s = 0.0f;
            for (int r = 0; r < len; r++) s += src[base + r * DDIM];
            As[m][kk] = s * sm_inv[m];
        }
        // ---- B tile: g_WT[kc..kc+KC)[0..NPAD) via float4 ----
        {
            const float4* wt4 = (const float4*)(g_WT + kc * NPAD);
            float4* bs4 = (float4*)&Bs[0][0];
            #pragma unroll
            for (int j = 0; j < 5; j++) {
                int e4 = t + 256 * j;        // 1280 float4
                bs4[e4] = wt4[e4];
            }
        }
        __syncthreads();
        // ---- compute ----
        #pragma unroll
        for (int kk = 0; kk < KC; kk++) {
            unsigned long long a2[4];
            #pragma unroll
            for (int mm = 0; mm < 4; mm++) {
                unsigned int ab = __float_as_uint(As[ty * 4 + mm][kk]);
                asm("mov.b64 %0, {%1, %1};" : "=l"(a2[mm]) : "r"(ab));
            }
            #pragma unroll
            for (int i = 0; i < 5; i++) {
                int p = tx + 32 * i;
                unsigned long long bp =
                    *(const unsigned long long*)&Bs[kk][2 * p];
                #pragma unroll
                for (int mm = 0; mm < 4; mm++)
                    asm("fma.rn.f32x2 %0, %1, %2, %0;"
                        : "+l"(acc[mm][i]) : "l"(a2[mm]), "l"(bp));
            }
        }
        __syncthreads();
    }

    // ---- epilogue: bias + LayerNorm + write h + score dot ----
    const float inv_out = 1.0f / (float)OUTD;
    const int region_base = isK ? HK_OFF : H1_OFF;
    const float bsc = b_score[0];
    #pragma unroll
    for (int mm = 0; mm < 4; mm++) {
        const int m = ty * 4 + mm;
        const int g = tilebase + m;
        float lo[5], hi[5];
        float ssum = 0.0f;
        #pragma unroll
        for (int i = 0; i < 5; i++) {
            unsigned int u0, u1;
            asm("mov.b64 {%0, %1}, %2;" : "=r"(u0), "=r"(u1) : "l"(acc[mm][i]));
            int n0 = 2 * (tx + 32 * i);
            lo[i] = __uint_as_float(u0) + sb[n0];
            hi[i] = __uint_as_float(u1) + sb[n0 + 1];
            ssum += lo[i] + hi[i];    // pad lanes contribute exact 0
        }
        #pragma unroll
        for (int o = 16; o; o >>= 1) ssum += __shfl_xor_sync(0xffffffffu, ssum, o);
        float mean = ssum * inv_out;
        float vs = 0.0f;
        #pragma unroll
        for (int i = 0; i < 5; i++) {
            if (i < 4 || tx < 22) {   // pairs p<150 are real (n<300)
                float d0 = lo[i] - mean, d1 = hi[i] - mean;
                vs += d0 * d0 + d1 * d1;
            }
        }
        #pragma unroll
        for (int o = 16; o; o >>= 1) vs += __shfl_xor_sync(0xffffffffu, vs, o);
        float rstd = rsqrtf(vs * inv_out + EPSV);
        float sc = 0.0f;
        float* orow = out + region_base + (long)g * OUTD;
        #pragma unroll
        for (int i = 0; i < 5; i++) {
            if (i < 4 || tx < 22) {
                int n0 = 2 * (tx + 32 * i);
                float h0 = (lo[i] - mean) * rstd * sg[n0]     + sbe[n0];
                float h1 = (hi[i] - mean) * rstd * sg[n0 + 1] + sbe[n0 + 1];
                *(float2*)(orow + n0) = make_float2(h0, h1);
                sc += h0 * sw[n0] + h1 * sw[n0 + 1];
            }
        }
        #pragma unroll
        for (int o = 16; o; o >>= 1) sc += __shfl_xor_sync(0xffffffffu, sc, o);
        if (tx == 0)
            g_scores[(isK ? NB * L1 : 0) + g] = sc + bsc;
    }
}

// ---------------------------------------------------------------------------
// Softmax (masked) + score broadcast (branch1), and know softmax -> sk.
// Blocks 0..63: branch1 batch b. Blocks 64..127: know batch b-64.
// ---------------------------------------------------------------------------
__global__ __launch_bounds__(128)
void softmax_kernel(const void* __restrict__ mask1, const void* __restrict__ maskk,
                    float* __restrict__ out) {
    const int mode = g_mask_mode;
    const int t = threadIdx.x;
    if (blockIdx.x < NB) {
        const int b = blockIdx.x;
        __shared__ float red[4];
        __shared__ float sh[L1];
        float scv = g_scores[b * L1 + t];
        bool msk = read_mask(mask1, b * L1 + t, mode);
        float val = msk ? -3.0e38f : scv;
        float mx = val;
        #pragma unroll
        for (int o = 16; o; o >>= 1) mx = fmaxf(mx, __shfl_xor_sync(0xffffffffu, mx, o));
        if ((t & 31) == 0) red[t >> 5] = mx;
        __syncthreads();
        mx = fmaxf(fmaxf(red[0], red[1]), fmaxf(red[2], red[3]));
        __syncthreads();
        float ex = msk ? 0.0f : expf(scv - mx);
        float sm = ex;
        #pragma unroll
        for (int o = 16; o; o >>= 1) sm += __shfl_xor_sync(0xffffffffu, sm, o);
        if ((t & 31) == 0) red[t >> 5] = sm;
        __syncthreads();
        sm = red[0] + red[1] + red[2] + red[3];
        sh[t] = ex / sm;
        __syncthreads();
        // broadcast to (L1, OUTD) as float4 (OUTD % 4 == 0)
        float4* o4 = (float4*)(out + SCORE_OFF + (long)b * L1 * OUTD);
        const int Q = OUTD / 4; // 75
        for (int w = t; w < L1 * Q; w += 128) {
            int row = w / Q, q = w - row * Q;
            float p = sh[row];
            o4[row * Q + q] = make_float4(p, p, p, p);
        }
    } else {
        const int b = blockIdx.x - NB;
        if (t < 32) {
            bool msk = true;
            float scv = 0.0f;
            if (t < KN) {
                msk = read_mask(maskk, b * KN + t, mode);
                scv = g_scores[NB * L1 + b * KN + t];
            }
            float val = (t < KN && !msk) ? scv : -3.0e38f;
            float mx = val;
            #pragma unroll
            for (int o = 16; o; o >>= 1) mx = fmaxf(mx, __shfl_xor_sync(0xffffffffu, mx, o));
            float ex = (t < KN && !msk) ? expf(scv - mx) : 0.0f;
            float sm = ex;
            #pragma unroll
            for (int o = 16; o; o >>= 1) sm += __shfl_xor_sync(0xffffffffu, sm, o);
            if (t < KN) out[SK_OFF + b * KN + t] = ex / sm;
        }
    }
}

extern "C" void kernel_launch(void* const* d_in, const int* in_sizes, int n_in,
                              void* d_out, int out_size) {
    const float* t1    = (const float*)d_in[0];
    const float* know  = (const float*)d_in[1];
    const int*   s1s   = (const int*)d_in[2];
    const int*   s1e   = (const int*)d_in[3];
    const void*  mask1 = d_in[4];
    const int*   sks   = (const int*)d_in[5];
    const int*   ske   = (const int*)d_in[6];
    const void*  maskk = d_in[7];
    const float* W     = (const float*)d_in[8];
    const float* bl    = (const float*)d_in[9];
    const float* gm    = (const float*)d_in[10];
    const float* bt    = (const float*)d_in[11];
    const float* ws    = (const float*)d_in[12];
    const float* bs    = (const float*)d_in[13];
    float* out = (float*)d_out;

    detect_mask_kernel<<<1, 256>>>((const unsigned char*)maskk,
                                   (const unsigned char*)mask1);
    transpose_w_kernel<<<dim3(DDIM / 32, NPAD / 32), dim3(32, 8)>>>(W);
    gemm_ln_kernel<<<NBLK, 256>>>(t1, know, s1s, s1e, sks, ske,
                                  bl, gm, bt, ws, bs, out);
    softmax_kernel<<<2 * NB, 128>>>(mask1, maskk, out);
}